// round 2
// baseline (speedup 1.0000x reference)
#include <cuda_runtime.h>
#include <mma.h>

using namespace nvcuda;

#define NN  5000
#define BB  64
#define CC  64
#define DD  10
#define BCC 4096      // B*C
#define KW  8192      // cheb_k * C_in * C_out = 2*64*64

// Scratch (device globals: allocation-free at runtime)
__device__ float g_S [(long)NN * NN];    // softmax adjacency   (100 MB)
__device__ float g_Xr[(long)NN * BCC];   // x packed to (N, B*C) (82 MB)
__device__ float g_Y [(long)NN * BCC];   // S @ Xr               (82 MB)
__device__ float g_W [(long)NN * KW];    // per-node weights     (164 MB)

// ---------------------------------------------------------------------------
// Kernel 1: row-wise softmax(relu(E E^T)) -> g_S.  One block per row.
// ---------------------------------------------------------------------------
__global__ void __launch_bounds__(256) softmax_kernel(const float* __restrict__ E)
{
    __shared__ float row[NN];           // 20 KB
    __shared__ float red[8];
    __shared__ float sinv;

    int n   = blockIdx.x;
    int tid = threadIdx.x;

    float e[DD];
#pragma unroll
    for (int d = 0; d < DD; d++) e[d] = E[n * DD + d];

    float lsum = 0.f;
    for (int m = tid; m < NN; m += 256) {
        const float* Em = E + m * DD;
        float dot = 0.f;
#pragma unroll
        for (int d = 0; d < DD; d++) dot = fmaf(e[d], Em[d], dot);
        float ex = __expf(fmaxf(dot, 0.f));   // logits bounded (~<40): no max-shift needed
        row[m] = ex;
        lsum += ex;
    }
    // block reduction
    for (int off = 16; off; off >>= 1) lsum += __shfl_down_sync(0xffffffffu, lsum, off);
    if ((tid & 31) == 0) red[tid >> 5] = lsum;
    __syncthreads();
    if (tid == 0) {
        float t = 0.f;
#pragma unroll
        for (int w = 0; w < 8; w++) t += red[w];
        sinv = 1.f / t;
    }
    __syncthreads();
    float inv = sinv;
    long base = (long)n * NN;
    for (int m = tid; m < NN; m += 256)
        g_S[base + m] = row[m] * inv;
}

// ---------------------------------------------------------------------------
// Kernel 2: pack x (B,N,C) -> Xr (N, B*C)
// ---------------------------------------------------------------------------
__global__ void __launch_bounds__(256) pack_kernel(const float* __restrict__ x)
{
    int gid = blockIdx.x * 256 + threadIdx.x;  // exactly 5,120,000 float4s
    int n   = gid >> 10;
    int r   = gid & 1023;
    int b   = r >> 4;
    int c4  = r & 15;
    float4 v = *reinterpret_cast<const float4*>(x + ((long)b * NN + n) * CC + c4 * 4);
    *reinterpret_cast<float4*>(g_Xr + (long)n * BCC + b * CC + c4 * 4) = v;
}

// ---------------------------------------------------------------------------
// Kernel 3: W[n, kc*64*64] = sum_d E[n,d] * Wp[d, kc, i, o]   (layout matches:
// g_W[n][icat*64 + o] with icat = k*64 + i)
// ---------------------------------------------------------------------------
__global__ void __launch_bounds__(256) wpool_kernel(const float* __restrict__ E,
                                                    const float* __restrict__ Wp)
{
    int n  = blockIdx.y;
    int j4 = blockIdx.x * 256 + threadIdx.x;   // 0..2047 (float4 index in 8192)
    float e[DD];
#pragma unroll
    for (int d = 0; d < DD; d++) e[d] = E[n * DD + d];
    float4 acc = make_float4(0.f, 0.f, 0.f, 0.f);
#pragma unroll
    for (int d = 0; d < DD; d++) {
        float4 w = *reinterpret_cast<const float4*>(Wp + d * KW + j4 * 4);
        acc.x = fmaf(e[d], w.x, acc.x);
        acc.y = fmaf(e[d], w.y, acc.y);
        acc.z = fmaf(e[d], w.z, acc.z);
        acc.w = fmaf(e[d], w.w, acc.w);
    }
    *reinterpret_cast<float4*>(g_W + (long)n * KW + j4 * 4) = acc;
}

// ---------------------------------------------------------------------------
// Kernel 4: Y = S @ Xr   (M=5000, K=5000, Ncols=4096), tf32 WMMA, 128x128x16
// tiles, double-buffered smem (static, 32 KB).
// ---------------------------------------------------------------------------
#define BM 128
#define BN 128
#define BK 16
#define KTILES 313   // ceil(5000/16)

__global__ void __launch_bounds__(256) gemm_kernel()
{
    __shared__ __align__(16) float As[2][BM * BK];  // 2 x 8 KB
    __shared__ __align__(16) float Bs[2][BK * BN];  // 2 x 8 KB

    int tid  = threadIdx.x;
    int bx   = blockIdx.x, by = blockIdx.y;
    int wid  = tid >> 5;
    int lane = tid & 31;
    int wr   = wid >> 1;        // 0..3 : 32-row band
    int wc   = wid & 1;         // 0..1 : 64-col band

    wmma::fragment<wmma::accumulator, 16, 16, 8, float> acc[2][4];
#pragma unroll
    for (int i = 0; i < 2; i++)
#pragma unroll
        for (int j = 0; j < 4; j++) wmma::fill_fragment(acc[i][j], 0.f);

    float4 ra[2], rb[2];

    auto fetch = [&](int kt) {
#pragma unroll
        for (int it = 0; it < 2; it++) {            // A: 128x16 = 512 float4
            int f = it * 256 + tid;
            int r = f >> 2, c4 = f & 3;
            int gr = by * BM + r;
            int gk = kt * BK + c4 * 4;
            float4 v = make_float4(0.f, 0.f, 0.f, 0.f);
            if (gr < NN && gk + 3 < NN)
                v = *reinterpret_cast<const float4*>(g_S + (long)gr * NN + gk);
            ra[it] = v;
        }
#pragma unroll
        for (int it = 0; it < 2; it++) {            // B: 16x128 = 512 float4
            int f = it * 256 + tid;
            int r = f >> 5, c4 = f & 31;
            int gk = kt * BK + r;
            int gn = bx * BN + c4 * 4;
            float4 v = make_float4(0.f, 0.f, 0.f, 0.f);
            if (gk < NN)
                v = *reinterpret_cast<const float4*>(g_Xr + (long)gk * BCC + gn);
            rb[it] = v;
        }
    };
    auto store = [&](int s) {
#pragma unroll
        for (int it = 0; it < 2; it++) {
            int f = it * 256 + tid;
            int r = f >> 2, c4 = f & 3;
            float* p = &As[s][r * BK + c4 * 4];
            p[0] = wmma::__float_to_tf32(ra[it].x);
            p[1] = wmma::__float_to_tf32(ra[it].y);
            p[2] = wmma::__float_to_tf32(ra[it].z);
            p[3] = wmma::__float_to_tf32(ra[it].w);
        }
#pragma unroll
        for (int it = 0; it < 2; it++) {
            int f = it * 256 + tid;
            int r = f >> 5, c4 = f & 31;
            float* p = &Bs[s][r * BN + c4 * 4];
            p[0] = wmma::__float_to_tf32(rb[it].x);
            p[1] = wmma::__float_to_tf32(rb[it].y);
            p[2] = wmma::__float_to_tf32(rb[it].z);
            p[3] = wmma::__float_to_tf32(rb[it].w);
        }
    };

    fetch(0);
    store(0);
    __syncthreads();

    for (int kt = 0; kt < KTILES; kt++) {
        int s = kt & 1;
        if (kt + 1 < KTILES) fetch(kt + 1);     // global loads overlap compute
#pragma unroll
        for (int kk = 0; kk < 2; kk++) {
            wmma::fragment<wmma::matrix_a, 16, 16, 8, wmma::precision::tf32, wmma::row_major> af[2];
            wmma::fragment<wmma::matrix_b, 16, 16, 8, wmma::precision::tf32, wmma::row_major> bf[4];
#pragma unroll
            for (int i = 0; i < 2; i++)
                wmma::load_matrix_sync(af[i], &As[s][(wr * 32 + i * 16) * BK + kk * 8], BK);
#pragma unroll
            for (int j = 0; j < 4; j++)
                wmma::load_matrix_sync(bf[j], &Bs[s][(kk * 8) * BN + wc * 64 + j * 16], BN);
#pragma unroll
            for (int i = 0; i < 2; i++)
#pragma unroll
                for (int j = 0; j < 4; j++)
                    wmma::mma_sync(acc[i][j], af[i], bf[j], acc[i][j]);
        }
        if (kt + 1 < KTILES) {
            store((kt + 1) & 1);    // safe: buffer s^1 not read since kt-1's sync
            __syncthreads();
        }
    }

    // staged writeback with M-edge guards
    __syncthreads();
    float* stage = &As[0][0] + wid * 256;       // 16x16 per warp
#pragma unroll
    for (int i = 0; i < 2; i++)
#pragma unroll
        for (int j = 0; j < 4; j++) {
            __syncwarp();
            wmma::store_matrix_sync(stage, acc[i][j], 16, wmma::mem_row_major);
            __syncwarp();
            int grow = by * BM + wr * 32 + i * 16;
            int gcol = bx * BN + wc * 64 + j * 16;
            for (int e = lane; e < 64; e += 32) {
                int r = e >> 2, c4 = e & 3;
                if (grow + r < NN)
                    *reinterpret_cast<float4*>(g_Y + (long)(grow + r) * BCC + gcol + c4 * 4)
                        = *reinterpret_cast<const float4*>(stage + r * 16 + c4 * 4);
            }
        }
}

// ---------------------------------------------------------------------------
// Kernel 5: per-node epilogue.  out[b,n,o] = [x(b,n,:) | Y(n,b,:)] @ W[n] + bias[n]
// One block per node: 64x64 output, K=128, fp32.
// ---------------------------------------------------------------------------
__global__ void __launch_bounds__(256) epilogue_kernel(const float* __restrict__ E,
                                                       const float* __restrict__ bp,
                                                       float* __restrict__ out)
{
    __shared__ __align__(16) float Xs[64 * 132];   // pitch 132: conflict-free
    __shared__ float bs[64];

    int n   = blockIdx.x;
    int tid = threadIdx.x;

    // Xs[b][0:64] = x(b,n,:) = Xr[n][b*64..]; Xs[b][64:128] = Y[n][b*64..]
#pragma unroll
    for (int it = 0; it < 4; it++) {
        int idx = it * 256 + tid;
        int b = idx >> 4, c4 = idx & 15;
        float4 v0 = *reinterpret_cast<const float4*>(g_Xr + (long)n * BCC + b * 64 + c4 * 4);
        *reinterpret_cast<float4*>(&Xs[b * 132 + c4 * 4]) = v0;
        float4 v1 = *reinterpret_cast<const float4*>(g_Y + (long)n * BCC + b * 64 + c4 * 4);
        *reinterpret_cast<float4*>(&Xs[b * 132 + 64 + c4 * 4]) = v1;
    }
    if (tid < 64) {
        float s = 0.f;
#pragma unroll
        for (int d = 0; d < DD; d++) s = fmaf(E[n * DD + d], bp[d * 64 + tid], s);
        bs[tid] = s;
    }
    __syncthreads();

    int ty = tid >> 4, tx = tid & 15;
    int b0 = ty * 4, o0 = tx * 4;
    float acc[4][4];
#pragma unroll
    for (int j = 0; j < 4; j++)
#pragma unroll
        for (int k = 0; k < 4; k++) acc[j][k] = 0.f;

    const float4* Wn = reinterpret_cast<const float4*>(g_W + (long)n * KW);
#pragma unroll 4
    for (int i = 0; i < 128; i++) {
        float4 w = __ldg(Wn + i * 16 + tx);     // W[icat=i][o0..o0+3], L1-resident
        float a0 = Xs[(b0 + 0) * 132 + i];
        float a1 = Xs[(b0 + 1) * 132 + i];
        float a2 = Xs[(b0 + 2) * 132 + i];
        float a3 = Xs[(b0 + 3) * 132 + i];
        acc[0][0] = fmaf(a0, w.x, acc[0][0]);
        acc[0][1] = fmaf(a0, w.y, acc[0][1]);
        acc[0][2] = fmaf(a0, w.z, acc[0][2]);
        acc[0][3] = fmaf(a0, w.w, acc[0][3]);
        acc[1][0] = fmaf(a1, w.x, acc[1][0]);
        acc[1][1] = fmaf(a1, w.y, acc[1][1]);
        acc[1][2] = fmaf(a1, w.z, acc[1][2]);
        acc[1][3] = fmaf(a1, w.w, acc[1][3]);
        acc[2][0] = fmaf(a2, w.x, acc[2][0]);
        acc[2][1] = fmaf(a2, w.y, acc[2][1]);
        acc[2][2] = fmaf(a2, w.z, acc[2][2]);
        acc[2][3] = fmaf(a2, w.w, acc[2][3]);
        acc[3][0] = fmaf(a3, w.x, acc[3][0]);
        acc[3][1] = fmaf(a3, w.y, acc[3][1]);
        acc[3][2] = fmaf(a3, w.z, acc[3][2]);
        acc[3][3] = fmaf(a3, w.w, acc[3][3]);
    }

#pragma unroll
    for (int j = 0; j < 4; j++) {
        int b = b0 + j;
        float4 r;
        r.x = acc[j][0] + bs[o0 + 0];
        r.y = acc[j][1] + bs[o0 + 1];
        r.z = acc[j][2] + bs[o0 + 2];
        r.w = acc[j][3] + bs[o0 + 3];
        *reinterpret_cast<float4*>(out + ((long)b * NN + n) * CC + o0) = r;
    }
}

// ---------------------------------------------------------------------------
extern "C" void kernel_launch(void* const* d_in, const int* in_sizes, int n_in,
                              void* d_out, int out_size)
{
    const float* x  = (const float*)d_in[0];   // (64, 5000, 64)
    const float* E  = (const float*)d_in[1];   // (5000, 10)
    const float* Wp = (const float*)d_in[2];   // (10, 2, 64, 64)
    const float* bp = (const float*)d_in[3];   // (10, 64)
    float* out = (float*)d_out;                // (64, 5000, 64)

    softmax_kernel<<<NN, 256>>>(E);
    pack_kernel<<<20000, 256>>>(x);
    wpool_kernel<<<dim3(8, NN), 256>>>(E, Wp);
    gemm_kernel<<<dim3(BCC / BN, (NN + BM - 1) / BM), 256>>>();
    epilogue_kernel<<<NN, 256>>>(E, bp, out);

    (void)in_sizes; (void)n_in; (void)out_size;
}

// round 4
// speedup vs baseline: 1.2179x; 1.2179x over previous
#include <cuda_runtime.h>
#include <cuda_pipeline.h>
#include <mma.h>

using namespace nvcuda;

#define NN  5000
#define BB  64
#define CC  64
#define DD  10
#define BCC 4096      // B*C
#define KW  8192      // cheb_k * C_in * C_out = 2*64*64

// Scratch (device globals: allocation-free at runtime)
__device__ float g_S [(long)NN * NN];    // softmax adjacency, tf32-rounded (100 MB)
__device__ float g_Xr[(long)NN * BCC];   // x packed (N, B*C), fp32 (82 MB)
__device__ float g_Xt[(long)NN * BCC];   // x packed (N, B*C), tf32-rounded (82 MB)
__device__ float g_Y [(long)NN * BCC];   // S @ Xr               (82 MB)
__device__ float g_W [(long)NN * KW];    // per-node weights     (164 MB)

// ---------------------------------------------------------------------------
// Kernel 1: row-wise softmax(relu(E E^T)) -> g_S (tf32 RN rounded at source).
// ---------------------------------------------------------------------------
__global__ void __launch_bounds__(256) softmax_kernel(const float* __restrict__ E)
{
    __shared__ float row[NN];           // 20 KB
    __shared__ float red[8];
    __shared__ float sinv;

    int n   = blockIdx.x;
    int tid = threadIdx.x;

    float e[DD];
#pragma unroll
    for (int d = 0; d < DD; d++) e[d] = E[n * DD + d];

    float lsum = 0.f;
    for (int m = tid; m < NN; m += 256) {
        const float* Em = E + m * DD;
        float dot = 0.f;
#pragma unroll
        for (int d = 0; d < DD; d++) dot = fmaf(e[d], Em[d], dot);
        float ex = __expf(fmaxf(dot, 0.f));   // logits bounded: no max-shift needed
        row[m] = ex;
        lsum += ex;
    }
    for (int off = 16; off; off >>= 1) lsum += __shfl_down_sync(0xffffffffu, lsum, off);
    if ((tid & 31) == 0) red[tid >> 5] = lsum;
    __syncthreads();
    if (tid == 0) {
        float t = 0.f;
#pragma unroll
        for (int w = 0; w < 8; w++) t += red[w];
        sinv = 1.f / t;
    }
    __syncthreads();
    float inv = sinv;
    long base = (long)n * NN;
    for (int m = tid; m < NN; m += 256)
        g_S[base + m] = wmma::__float_to_tf32(row[m] * inv);
}

// ---------------------------------------------------------------------------
// Kernel 2: pack x (B,N,C) -> Xr fp32 (epilogue) and Xt tf32 (GEMM B operand)
// ---------------------------------------------------------------------------
__global__ void __launch_bounds__(256) pack_kernel(const float* __restrict__ x)
{
    int gid = blockIdx.x * 256 + threadIdx.x;  // exactly 5,120,000 float4s
    int n   = gid >> 10;
    int r   = gid & 1023;
    int b   = r >> 4;
    int c4  = r & 15;
    float4 v = *reinterpret_cast<const float4*>(x + ((long)b * NN + n) * CC + c4 * 4);
    long o = (long)n * BCC + b * CC + c4 * 4;
    *reinterpret_cast<float4*>(g_Xr + o) = v;
    float4 t;
    t.x = wmma::__float_to_tf32(v.x);
    t.y = wmma::__float_to_tf32(v.y);
    t.z = wmma::__float_to_tf32(v.z);
    t.w = wmma::__float_to_tf32(v.w);
    *reinterpret_cast<float4*>(g_Xt + o) = t;
}

// ---------------------------------------------------------------------------
// Kernel 3: W[n, kc*64*64] = sum_d E[n,d] * Wp[d, kc, i, o]
// ---------------------------------------------------------------------------
__global__ void __launch_bounds__(256) wpool_kernel(const float* __restrict__ E,
                                                    const float* __restrict__ Wp)
{
    int n  = blockIdx.y;
    int j4 = blockIdx.x * 256 + threadIdx.x;   // 0..2047 (float4 index in 8192)
    float e[DD];
#pragma unroll
    for (int d = 0; d < DD; d++) e[d] = E[n * DD + d];
    float4 acc = make_float4(0.f, 0.f, 0.f, 0.f);
#pragma unroll
    for (int d = 0; d < DD; d++) {
        float4 w = *reinterpret_cast<const float4*>(Wp + d * KW + j4 * 4);
        acc.x = fmaf(e[d], w.x, acc.x);
        acc.y = fmaf(e[d], w.y, acc.y);
        acc.z = fmaf(e[d], w.z, acc.z);
        acc.w = fmaf(e[d], w.w, acc.w);
    }
    *reinterpret_cast<float4*>(g_W + (long)n * KW + j4 * 4) = acc;
}

// ---------------------------------------------------------------------------
// Kernel 4: Y = S @ Xt  (M=5000, K=5000, Ncols=4096), tf32 WMMA.
// 128x128x16 block tile, 4 warps, 64x64 warp tile, cp.async double buffer,
// padded smem (A pitch 20, B pitch 132) -> conflict-free fragment loads.
// ---------------------------------------------------------------------------
#define BM 128
#define BN 128
#define BK 16
#define PA 20     // A smem pitch (floats)
#define PB 132    // B smem pitch (floats)
#define KTILES 313   // ceil(5000/16)

__global__ void __launch_bounds__(128) gemm_kernel()
{
    __shared__ __align__(16) float As[2][BM * PA];  // 2 x 10 KB
    __shared__ __align__(16) float Bs[2][BK * PB];  // 2 x 8.25 KB

    int tid  = threadIdx.x;
    int bx   = blockIdx.x, by = blockIdx.y;
    int wid  = tid >> 5;
    int lane = tid & 31;
    int wr   = wid >> 1;        // 0..1 : 64-row band
    int wc   = wid & 1;         // 0..1 : 64-col band

    wmma::fragment<wmma::accumulator, 16, 16, 8, float> acc[4][4];
#pragma unroll
    for (int i = 0; i < 4; i++)
#pragma unroll
        for (int j = 0; j < 4; j++) wmma::fill_fragment(acc[i][j], 0.f);

    // async fetch of K-tile kt into buffer s
    auto fetch = [&](int kt, int s) {
#pragma unroll
        for (int it = 0; it < 4; it++) {            // A: 128x16 = 512 float4
            int f = it * 128 + tid;
            int r = f >> 2, c4 = f & 3;
            int gr = by * BM + r;
            int gk = kt * BK + c4 * 4;
            bool ok = (gr < NN) && (gk < NN);       // NN%4==0: chunk all-in or all-out
            const float* src = ok ? (g_S + (long)gr * NN + gk) : g_S;
            __pipeline_memcpy_async(&As[s][r * PA + c4 * 4], src, 16, ok ? 0 : 16);
        }
#pragma unroll
        for (int it = 0; it < 4; it++) {            // B: 16x128 = 512 float4
            int f = it * 128 + tid;
            int r = f >> 5, c4 = f & 31;
            int gk = kt * BK + r;
            int gn = bx * BN + c4 * 4;
            bool ok = (gk < NN);
            const float* src = ok ? (g_Xt + (long)gk * BCC + gn) : g_Xt;
            __pipeline_memcpy_async(&Bs[s][r * PB + c4 * 4], src, 16, ok ? 0 : 16);
        }
        __pipeline_commit();
    };

    fetch(0, 0);
    __pipeline_wait_prior(0);
    __syncthreads();

    for (int kt = 0; kt < KTILES; kt++) {
        int s = kt & 1;
        if (kt + 1 < KTILES) fetch(kt + 1, s ^ 1);  // overlaps compute below
#pragma unroll
        for (int kk = 0; kk < 2; kk++) {
            wmma::fragment<wmma::matrix_a, 16, 16, 8, wmma::precision::tf32, wmma::row_major> af[4];
            wmma::fragment<wmma::matrix_b, 16, 16, 8, wmma::precision::tf32, wmma::row_major> bf[4];
#pragma unroll
            for (int i = 0; i < 4; i++)
                wmma::load_matrix_sync(af[i], &As[s][(wr * 64 + i * 16) * PA + kk * 8], PA);
#pragma unroll
            for (int j = 0; j < 4; j++)
                wmma::load_matrix_sync(bf[j], &Bs[s][(kk * 8) * PB + wc * 64 + j * 16], PB);
#pragma unroll
            for (int i = 0; i < 4; i++)
#pragma unroll
                for (int j = 0; j < 4; j++)
                    wmma::mma_sync(acc[i][j], af[i], bf[j], acc[i][j]);
        }
        __pipeline_wait_prior(0);
        __syncthreads();
    }

    if (by * BM + BM <= NN) {
        // interior block: direct global store
#pragma unroll
        for (int i = 0; i < 4; i++)
#pragma unroll
            for (int j = 0; j < 4; j++) {
                int grow = by * BM + wr * 64 + i * 16;
                int gcol = bx * BN + wc * 64 + j * 16;
                wmma::store_matrix_sync(g_Y + (long)grow * BCC + gcol, acc[i][j],
                                        BCC, wmma::mem_row_major);
            }
    } else {
        // edge block: stage through smem with row guards
        float* stage = &As[0][0] + wid * 256;       // 16x16 per warp
#pragma unroll
        for (int i = 0; i < 4; i++)
#pragma unroll
            for (int j = 0; j < 4; j++) {
                __syncwarp();
                wmma::store_matrix_sync(stage, acc[i][j], 16, wmma::mem_row_major);
                __syncwarp();
                int grow = by * BM + wr * 64 + i * 16;
                int gcol = bx * BN + wc * 64 + j * 16;
                for (int e = lane; e < 64; e += 32) {
                    int r = e >> 2, c4 = e & 3;
                    if (grow + r < NN)
                        *reinterpret_cast<float4*>(g_Y + (long)(grow + r) * BCC + gcol + c4 * 4)
                            = *reinterpret_cast<const float4*>(stage + r * 16 + c4 * 4);
                }
            }
    }
}

// ---------------------------------------------------------------------------
// Kernel 5: per-node epilogue.  out[b,n,o] = [x(b,n,:) | Y(n,b,:)] @ W[n] + bias[n]
// ---------------------------------------------------------------------------
__global__ void __launch_bounds__(256) epilogue_kernel(const float* __restrict__ E,
                                                       const float* __restrict__ bp,
                                                       float* __restrict__ out)
{
    __shared__ __align__(16) float Xs[64 * 132];   // pitch 132: conflict-free
    __shared__ float bs[64];

    int n   = blockIdx.x;
    int tid = threadIdx.x;

#pragma unroll
    for (int it = 0; it < 4; it++) {
        int idx = it * 256 + tid;
        int b = idx >> 4, c4 = idx & 15;
        float4 v0 = *reinterpret_cast<const float4*>(g_Xr + (long)n * BCC + b * 64 + c4 * 4);
        *reinterpret_cast<float4*>(&Xs[b * 132 + c4 * 4]) = v0;
        float4 v1 = *reinterpret_cast<const float4*>(g_Y + (long)n * BCC + b * 64 + c4 * 4);
        *reinterpret_cast<float4*>(&Xs[b * 132 + 64 + c4 * 4]) = v1;
    }
    if (tid < 64) {
        float s = 0.f;
#pragma unroll
        for (int d = 0; d < DD; d++) s = fmaf(E[n * DD + d], bp[d * 64 + tid], s);
        bs[tid] = s;
    }
    __syncthreads();

    int ty = tid >> 4, tx = tid & 15;
    int b0 = ty * 4, o0 = tx * 4;
    float acc[4][4];
#pragma unroll
    for (int j = 0; j < 4; j++)
#pragma unroll
        for (int k = 0; k < 4; k++) acc[j][k] = 0.f;

    const float4* Wn = reinterpret_cast<const float4*>(g_W + (long)n * KW);
#pragma unroll 4
    for (int i = 0; i < 128; i++) {
        float4 w = __ldg(Wn + i * 16 + tx);
        float a0 = Xs[(b0 + 0) * 132 + i];
        float a1 = Xs[(b0 + 1) * 132 + i];
        float a2 = Xs[(b0 + 2) * 132 + i];
        float a3 = Xs[(b0 + 3) * 132 + i];
        acc[0][0] = fmaf(a0, w.x, acc[0][0]);
        acc[0][1] = fmaf(a0, w.y, acc[0][1]);
        acc[0][2] = fmaf(a0, w.z, acc[0][2]);
        acc[0][3] = fmaf(a0, w.w, acc[0][3]);
        acc[1][0] = fmaf(a1, w.x, acc[1][0]);
        acc[1][1] = fmaf(a1, w.y, acc[1][1]);
        acc[1][2] = fmaf(a1, w.z, acc[1][2]);
        acc[1][3] = fmaf(a1, w.w, acc[1][3]);
        acc[2][0] = fmaf(a2, w.x, acc[2][0]);
        acc[2][1] = fmaf(a2, w.y, acc[2][1]);
        acc[2][2] = fmaf(a2, w.z, acc[2][2]);
        acc[2][3] = fmaf(a2, w.w, acc[2][3]);
        acc[3][0] = fmaf(a3, w.x, acc[3][0]);
        acc[3][1] = fmaf(a3, w.y, acc[3][1]);
        acc[3][2] = fmaf(a3, w.z, acc[3][2]);
        acc[3][3] = fmaf(a3, w.w, acc[3][3]);
    }

#pragma unroll
    for (int j = 0; j < 4; j++) {
        int b = b0 + j;
        float4 r;
        r.x = acc[j][0] + bs[o0 + 0];
        r.y = acc[j][1] + bs[o0 + 1];
        r.z = acc[j][2] + bs[o0 + 2];
        r.w = acc[j][3] + bs[o0 + 3];
        *reinterpret_cast<float4*>(out + ((long)b * NN + n) * CC + o0) = r;
    }
}

// ---------------------------------------------------------------------------
extern "C" void kernel_launch(void* const* d_in, const int* in_sizes, int n_in,
                              void* d_out, int out_size)
{
    const float* x  = (const float*)d_in[0];   // (64, 5000, 64)
    const float* E  = (const float*)d_in[1];   // (5000, 10)
    const float* Wp = (const float*)d_in[2];   // (10, 2, 64, 64)
    const float* bp = (const float*)d_in[3];   // (10, 64)
    float* out = (float*)d_out;                // (64, 5000, 64)

    softmax_kernel<<<NN, 256>>>(E);
    pack_kernel<<<20000, 256>>>(x);
    wpool_kernel<<<dim3(8, NN), 256>>>(E, Wp);
    gemm_kernel<<<dim3(BCC / BN, (NN + BM - 1) / BM), 128>>>();
    epilogue_kernel<<<NN, 256>>>(E, bp, out);

    (void)in_sizes; (void)n_in; (void)out_size;
}